// round 14
// baseline (speedup 1.0000x reference)
#include <cuda_runtime.h>

// ---------------- problem constants ----------------
#define T_TOTAL 35968706LL          // sum of all 52 weight-tensor sizes
#define NV (T_TOTAL / 2)            // float2 count per row (T even)
#define C5_BLOCKS 1568

// ---------------- device scratch (no allocs allowed) ----------------
__device__ float g_c1[4 * 4  * 112 * 112];
__device__ float g_c2[4 * 8  * 56  * 56];
__device__ float g_c3[4 * 16 * 28  * 28];
__device__ float g_c4[4 * 32 * 14  * 14];
__device__ float g_c5[4 * 64 * 7   * 7];
__device__ float g_q[64];                 // q[b][j]
__device__ unsigned g_cnt[4];             // arrive counter (self-reset each use)

// ---------------- split-K conv body: k=4, s=2, p=1 (R4-verified, 31 regs) ---
// Block = 256 threads = OPT outputs x G channel-groups, shared-mem reduce.
template<int CIN, int G, bool LRELU>
__device__ __forceinline__ void conv_body(
    const float* __restrict__ x, const float* __restrict__ w,
    const float* __restrict__ bias, float* __restrict__ y,
    int Hin, int Win, int Cout, int Hout, int Wout)
{
    constexpr int OPT = 256 / G;      // outputs per block
    constexpr int CPG = CIN / G;      // channels per group
    const int tid = threadIdx.x;
    const int g   = tid / OPT;
    const int ol  = tid % OPT;

    long long oidx = (long long)blockIdx.x * OPT + ol;
    int ow = (int)(oidx % Wout); long long t = oidx / Wout;
    int oh = (int)(t % Hout);    t /= Hout;
    int co = (int)(t % Cout);
    int n  = (int)(t / Cout);

    const int ih0 = oh * 2 - 1, iw0 = ow * 2 - 1;
    const float* xn = x + ((long long)n * CIN + g * CPG) * Hin * Win;
    const float* wc = w + ((long long)co * CIN + g * CPG) * 16;

    float acc = 0.f;
    #pragma unroll
    for (int ci = 0; ci < CPG; ci++) {
        const float* xc = xn + ci * Hin * Win;
        const float* wk = wc + ci * 16;
        #pragma unroll
        for (int kh = 0; kh < 4; kh++) {
            int ih = ih0 + kh;
            if ((unsigned)ih >= (unsigned)Hin) continue;
            const float* xr = xc + ih * Win;
            #pragma unroll
            for (int kw = 0; kw < 4; kw++) {
                int iw = iw0 + kw;
                if ((unsigned)iw < (unsigned)Win)
                    acc = fmaf(xr[iw], wk[kh * 4 + kw], acc);
            }
        }
    }

    if (G == 1) {
        acc += bias[co];
        if (LRELU) acc = (acc >= 0.f) ? acc : 0.01f * acc;
        y[oidx] = acc;
    } else {
        __shared__ float s[256];
        s[tid] = acc;
        __syncthreads();
        if (g == 0) {
            float sum = acc;
            #pragma unroll
            for (int j = 1; j < G; j++) sum += s[j * OPT + ol];
            sum += bias[co];
            if (LRELU) sum = (sum >= 0.f) ? sum : 0.01f * sum;
            y[oidx] = sum;
        }
    }
}

template<int CIN, int G, bool LRELU>
__global__ void __launch_bounds__(256)
conv_split(const float* __restrict__ x, const float* __restrict__ w,
           const float* __restrict__ bias, float* __restrict__ y,
           int Hin, int Win, int Cout, int Hout, int Wout)
{
    conv_body<CIN, G, LRELU>(x, w, bias, y, Hin, Win, Cout, Hout, Wout);
}

// ---------------- conv5 + head fused (arrive-last; no spinning) -------------
__global__ void __launch_bounds__(256)
conv5_head_k(const float* __restrict__ x, const float* __restrict__ w,
             const float* __restrict__ bias,
             const float* __restrict__ fc1w, const float* __restrict__ fc1b,
             const float* __restrict__ fc2w, const float* __restrict__ fc2b,
             const float* __restrict__ emb,
             float* __restrict__ loss_out)
{
    conv_body<32, 32, false>(x, w, bias, g_c5, 14, 14, 64, 7, 7);

    // arrive-only: 1567 blocks exit; the LAST arriver (whole block) does the head
    __shared__ int s_last;
    __syncthreads();
    if (threadIdx.x == 0) {
        __threadfence();                                 // release my g_c5 writes
        unsigned prev = atomicAdd(&g_cnt[0], 1u);
        if (prev == (unsigned)(C5_BLOCKS - 1)) {
            atomicSub(&g_cnt[0], (unsigned)C5_BLOCKS);   // self-reset for next replay
            __threadfence();                             // acquire all writers
            s_last = 1;
        } else s_last = 0;
    }
    __syncthreads();
    if (!s_last) return;

    __shared__ float sx[4][64];
    __shared__ float sh[4][16];
    __shared__ float se[4][16];
    __shared__ int   sidx[4];
    __shared__ float sred[64];
    int tid = threadIdx.x;

    {   // adaptive avg pool 7x7
        int b = tid >> 6, c = tid & 63;
        const float* p = g_c5 + (b * 64 + c) * 49;
        float s = 0.f;
        #pragma unroll
        for (int i = 0; i < 49; i++) s += p[i];
        sx[b][c] = s * (1.f / 49.f);
    }
    __syncthreads();

    if (tid < 64) {   // fc1 (64->16) + lrelu
        int b = tid >> 4, j = tid & 15;
        float s = fc1b[j];
        #pragma unroll
        for (int k = 0; k < 64; k++) s += sx[b][k] * fc1w[j * 64 + k];
        sh[b][j] = (s >= 0.f) ? s : 0.01f * s;
    }
    __syncthreads();

    if (tid < 64) {   // fc2 (16->16)
        int b = tid >> 4, j = tid & 15;
        float s = fc2b[j];
        #pragma unroll
        for (int k = 0; k < 16; k++) s += sh[b][k] * fc2w[j * 16 + k];
        se[b][j] = s;
    }
    __syncthreads();

    if (tid < 4) {    // VQ argmin (first-min like jnp.argmin)
        int b = tid;
        float ee = 0.f;
        #pragma unroll
        for (int j = 0; j < 16; j++) ee += se[b][j] * se[b][j];
        float best = __int_as_float(0x7f800000);
        int bi = 0;
        for (int c = 0; c < 4; c++) {
            float s2 = 0.f, dot = 0.f;
            #pragma unroll
            for (int j = 0; j < 16; j++) {
                float w2 = emb[c * 16 + j];
                s2  += w2 * w2;
                dot += w2 * se[b][j];
            }
            float d = ee + s2 - 2.f * dot;
            if (d < best) { best = d; bi = c; }
        }
        sidx[b] = bi;
    }
    __syncthreads();

    if (tid < 64) {   // q to global + loss = 1.25 * mean((q - e)^2)
        int b = tid >> 4, j = tid & 15;
        float qv = emb[sidx[b] * 16 + j];
        g_q[tid] = qv;
        float diff = qv - se[b][j];
        sred[tid] = diff * diff;
    }
    __syncthreads();
    if (tid == 0) {
        float s = 0.f;
        for (int i = 0; i < 64; i++) s += sred[i];
        *loss_out = 1.25f * s * (1.f / 64.f);
    }
}

// ---------------- the big streaming GEMM: out = q @ W_all (R4-verified) ----
__global__ void __launch_bounds__(256)
gemm_k(const float* __restrict__ W, float* __restrict__ out)
{
    __shared__ float sq[64];
    if (threadIdx.x < 64) sq[threadIdx.x] = g_q[threadIdx.x];
    __syncthreads();

    long long i = (long long)blockIdx.x * blockDim.x + threadIdx.x;
    if (i >= NV) return;

    const float2* __restrict__ W2 = (const float2*)W;
    float2 a0 = {0.f, 0.f}, a1 = {0.f, 0.f}, a2 = {0.f, 0.f}, a3 = {0.f, 0.f};

    #pragma unroll
    for (int k = 0; k < 16; k++) {
        float2 w = __ldcs(&W2[(long long)k * NV + i]);
        float q0 = sq[k], q1 = sq[16 + k], q2 = sq[32 + k], q3 = sq[48 + k];
        a0.x = fmaf(q0, w.x, a0.x); a0.y = fmaf(q0, w.y, a0.y);
        a1.x = fmaf(q1, w.x, a1.x); a1.y = fmaf(q1, w.y, a1.y);
        a2.x = fmaf(q2, w.x, a2.x); a2.y = fmaf(q2, w.y, a2.y);
        a3.x = fmaf(q3, w.x, a3.x); a3.y = fmaf(q3, w.y, a3.y);
    }

    float2* __restrict__ O2 = (float2*)out;
    __stcs(&O2[i],          a0);
    __stcs(&O2[NV + i],     a1);
    __stcs(&O2[2 * NV + i], a2);
    __stcs(&O2[3 * NV + i], a3);
}

// ---------------- launch ----------------
extern "C" void kernel_launch(void* const* d_in, const int* in_sizes, int n_in,
                              void* d_out, int out_size)
{
    const float* rgb   = (const float*)d_in[0];
    const float* cw1   = (const float*)d_in[1];
    const float* cb1   = (const float*)d_in[2];
    const float* cw2   = (const float*)d_in[3];
    const float* cb2   = (const float*)d_in[4];
    const float* cw3   = (const float*)d_in[5];
    const float* cb3   = (const float*)d_in[6];
    const float* cw4   = (const float*)d_in[7];
    const float* cb4   = (const float*)d_in[8];
    const float* cw5   = (const float*)d_in[9];
    const float* cb5   = (const float*)d_in[10];
    const float* fc1w  = (const float*)d_in[11];
    const float* fc1b  = (const float*)d_in[12];
    const float* fc2w  = (const float*)d_in[13];
    const float* fc2b  = (const float*)d_in[14];
    const float* emb   = (const float*)d_in[15];
    const float* Wall  = (const float*)d_in[16];
    float* out = (float*)d_out;

    float *c1, *c2, *c3, *c4;
    cudaGetSymbolAddress((void**)&c1, g_c1);
    cudaGetSymbolAddress((void**)&c2, g_c2);
    cudaGetSymbolAddress((void**)&c3, g_c3);
    cudaGetSymbolAddress((void**)&c4, g_c4);

    // outputs/layer:          200704    100352     50176     25088     12544
    // OPT (=256/G):              256        64        32        16         8
    // blocks:                    784      1568      1568      1568      1568
    conv_split<3, 1,  true ><<<784,  256>>>(rgb, cw1, cb1, c1, 224, 224, 4, 112, 112);
    conv_split<4, 4,  true ><<<1568, 256>>>(c1,  cw2, cb2, c2, 112, 112, 8,  56,  56);
    conv_split<8, 8,  true ><<<1568, 256>>>(c2,  cw3, cb3, c3,  56,  56, 16, 28,  28);
    conv_split<16,16, true ><<<1568, 256>>>(c3,  cw4, cb4, c4,  28,  28, 32, 14,  14);

    // conv5 + head fused (arrive-last; loss at the final output element)
    conv5_head_k<<<C5_BLOCKS, 256>>>(c4, cw5, cb5, fc1w, fc1b, fc2w, fc2b, emb,
                                     out + (long long)out_size - 1);

    // big streaming GEMM (byte-identical to the 454.8us best)
    const int TB = 256;
    long long nblocks = (NV + TB - 1) / TB;
    gemm_k<<<(unsigned)nblocks, TB>>>(Wall, out);
}

// round 16
// speedup vs baseline: 1.0138x; 1.0138x over previous
#include <cuda_runtime.h>

// ---------------- problem constants ----------------
#define T_TOTAL 35968706LL          // sum of all 52 weight-tensor sizes
#define NV (T_TOTAL / 2)            // float2 count per row (T even)
#define C5_BLOCKS 784

// ---------------- device scratch (no allocs allowed) ----------------
__device__ float g_c1[4 * 4  * 112 * 112];
__device__ float g_c2[4 * 8  * 56  * 56];
__device__ float g_c3[4 * 16 * 28  * 28];
__device__ float g_c4[4 * 32 * 14  * 14];
__device__ float g_c5[4 * 64 * 7   * 7];
__device__ float g_q[64];                 // q[b][j]
__device__ unsigned g_cnt[4];             // arrive counter (self-reset each use)

// ---------------- split-K conv body: k=4, s=2, p=1 ----------------
// ALL dims compile-time: div/mod -> mul-shift, guards -> immediate compares.
// Block = 256 threads = OPT outputs x G channel-groups, shared-mem reduce.
template<int CIN, int G, int HIN, int WIN, int COUT, bool LRELU>
__device__ __forceinline__ void conv_body(
    const float* __restrict__ x, const float* __restrict__ w,
    const float* __restrict__ bias, float* __restrict__ y)
{
    constexpr int HOUT = HIN / 2;
    constexpr int WOUT = WIN / 2;
    constexpr int OPT  = 256 / G;      // outputs per block
    constexpr int CPG  = CIN / G;      // channels per group
    const int tid = threadIdx.x;
    const int g   = tid / OPT;
    const int ol  = tid % OPT;

    int oidx = blockIdx.x * OPT + ol;   // < 4*COUT*HOUT*WOUT <= 200704, fits int
    int ow = oidx % WOUT; int t = oidx / WOUT;
    int oh = t % HOUT;    t /= HOUT;
    int co = t % COUT;    int n = t / COUT;

    const int ih0 = oh * 2 - 1, iw0 = ow * 2 - 1;
    const float* xn = x + (n * CIN + g * CPG) * (HIN * WIN);
    const float* wc = w + (co * CIN + g * CPG) * 16;

    float acc = 0.f;
    #pragma unroll
    for (int ci = 0; ci < CPG; ci++) {
        const float* xc = xn + ci * (HIN * WIN);
        const float* wk = wc + ci * 16;
        #pragma unroll
        for (int kh = 0; kh < 4; kh++) {
            int ih = ih0 + kh;
            if ((unsigned)ih >= (unsigned)HIN) continue;
            const float* xr = xc + ih * WIN;
            #pragma unroll
            for (int kw = 0; kw < 4; kw++) {
                int iw = iw0 + kw;
                if ((unsigned)iw < (unsigned)WIN)
                    acc = fmaf(xr[iw], wk[kh * 4 + kw], acc);
            }
        }
    }

    if (G == 1) {
        acc += bias[co];
        if (LRELU) acc = (acc >= 0.f) ? acc : 0.01f * acc;
        y[oidx] = acc;
    } else {
        __shared__ float s[256];
        s[tid] = acc;
        __syncthreads();
        if (g == 0) {
            float sum = acc;
            #pragma unroll
            for (int j = 1; j < G; j++) sum += s[j * OPT + ol];
            sum += bias[co];
            if (LRELU) sum = (sum >= 0.f) ? sum : 0.01f * sum;
            y[oidx] = sum;
        }
    }
}

template<int CIN, int G, int HIN, int WIN, int COUT, bool LRELU>
__global__ void __launch_bounds__(256)
conv_split(const float* __restrict__ x, const float* __restrict__ w,
           const float* __restrict__ bias, float* __restrict__ y)
{
    conv_body<CIN, G, HIN, WIN, COUT, LRELU>(x, w, bias, y);
}

// ---------------- conv5 + head fused (arrive-last; no spinning) -------------
__global__ void __launch_bounds__(256)
conv5_head_k(const float* __restrict__ x, const float* __restrict__ w,
             const float* __restrict__ bias,
             const float* __restrict__ fc1w, const float* __restrict__ fc1b,
             const float* __restrict__ fc2w, const float* __restrict__ fc2b,
             const float* __restrict__ emb,
             float* __restrict__ loss_out)
{
    conv_body<32, 16, 14, 14, 64, false>(x, w, bias, g_c5);

    // arrive-only: 783 blocks exit; the LAST arriver (whole block) does the head
    __shared__ int s_last;
    __syncthreads();
    if (threadIdx.x == 0) {
        __threadfence();                                 // release my g_c5 writes
        unsigned prev = atomicAdd(&g_cnt[0], 1u);
        if (prev == (unsigned)(C5_BLOCKS - 1)) {
            atomicSub(&g_cnt[0], (unsigned)C5_BLOCKS);   // self-reset for next replay
            __threadfence();                             // acquire all writers
            s_last = 1;
        } else s_last = 0;
    }
    __syncthreads();
    if (!s_last) return;

    __shared__ float sx[4][64];
    __shared__ float sh[4][16];
    __shared__ float se[4][16];
    __shared__ int   sidx[4];
    __shared__ float sred[64];
    int tid = threadIdx.x;

    {   // adaptive avg pool 7x7
        int b = tid >> 6, c = tid & 63;
        const float* p = g_c5 + (b * 64 + c) * 49;
        float s = 0.f;
        #pragma unroll
        for (int i = 0; i < 49; i++) s += p[i];
        sx[b][c] = s * (1.f / 49.f);
    }
    __syncthreads();

    if (tid < 64) {   // fc1 (64->16) + lrelu
        int b = tid >> 4, j = tid & 15;
        float s = fc1b[j];
        #pragma unroll
        for (int k = 0; k < 64; k++) s += sx[b][k] * fc1w[j * 64 + k];
        sh[b][j] = (s >= 0.f) ? s : 0.01f * s;
    }
    __syncthreads();

    if (tid < 64) {   // fc2 (16->16)
        int b = tid >> 4, j = tid & 15;
        float s = fc2b[j];
        #pragma unroll
        for (int k = 0; k < 16; k++) s += sh[b][k] * fc2w[j * 16 + k];
        se[b][j] = s;
    }
    __syncthreads();

    if (tid < 4) {    // VQ argmin (first-min like jnp.argmin)
        int b = tid;
        float ee = 0.f;
        #pragma unroll
        for (int j = 0; j < 16; j++) ee += se[b][j] * se[b][j];
        float best = __int_as_float(0x7f800000);
        int bi = 0;
        for (int c = 0; c < 4; c++) {
            float s2 = 0.f, dot = 0.f;
            #pragma unroll
            for (int j = 0; j < 16; j++) {
                float w2 = emb[c * 16 + j];
                s2  += w2 * w2;
                dot += w2 * se[b][j];
            }
            float d = ee + s2 - 2.f * dot;
            if (d < best) { best = d; bi = c; }
        }
        sidx[b] = bi;
    }
    __syncthreads();

    if (tid < 64) {   // q to global + loss = 1.25 * mean((q - e)^2)
        int b = tid >> 4, j = tid & 15;
        float qv = emb[sidx[b] * 16 + j];
        g_q[tid] = qv;
        float diff = qv - se[b][j];
        sred[tid] = diff * diff;
    }
    __syncthreads();
    if (tid == 0) {
        float s = 0.f;
        for (int i = 0; i < 64; i++) s += sred[i];
        *loss_out = 1.25f * s * (1.f / 64.f);
    }
}

// ---------------- the big streaming GEMM: out = q @ W_all (R4-verified) ----
__global__ void __launch_bounds__(256)
gemm_k(const float* __restrict__ W, float* __restrict__ out)
{
    __shared__ float sq[64];
    if (threadIdx.x < 64) sq[threadIdx.x] = g_q[threadIdx.x];
    __syncthreads();

    long long i = (long long)blockIdx.x * blockDim.x + threadIdx.x;
    if (i >= NV) return;

    const float2* __restrict__ W2 = (const float2*)W;
    float2 a0 = {0.f, 0.f}, a1 = {0.f, 0.f}, a2 = {0.f, 0.f}, a3 = {0.f, 0.f};

    #pragma unroll
    for (int k = 0; k < 16; k++) {
        float2 w = __ldcs(&W2[(long long)k * NV + i]);
        float q0 = sq[k], q1 = sq[16 + k], q2 = sq[32 + k], q3 = sq[48 + k];
        a0.x = fmaf(q0, w.x, a0.x); a0.y = fmaf(q0, w.y, a0.y);
        a1.x = fmaf(q1, w.x, a1.x); a1.y = fmaf(q1, w.y, a1.y);
        a2.x = fmaf(q2, w.x, a2.x); a2.y = fmaf(q2, w.y, a2.y);
        a3.x = fmaf(q3, w.x, a3.x); a3.y = fmaf(q3, w.y, a3.y);
    }

    float2* __restrict__ O2 = (float2*)out;
    __stcs(&O2[i],          a0);
    __stcs(&O2[NV + i],     a1);
    __stcs(&O2[2 * NV + i], a2);
    __stcs(&O2[3 * NV + i], a3);
}

// ---------------- launch ----------------
extern "C" void kernel_launch(void* const* d_in, const int* in_sizes, int n_in,
                              void* d_out, int out_size)
{
    const float* rgb   = (const float*)d_in[0];
    const float* cw1   = (const float*)d_in[1];
    const float* cb1   = (const float*)d_in[2];
    const float* cw2   = (const float*)d_in[3];
    const float* cb2   = (const float*)d_in[4];
    const float* cw3   = (const float*)d_in[5];
    const float* cb3   = (const float*)d_in[6];
    const float* cw4   = (const float*)d_in[7];
    const float* cb4   = (const float*)d_in[8];
    const float* cw5   = (const float*)d_in[9];
    const float* cb5   = (const float*)d_in[10];
    const float* fc1w  = (const float*)d_in[11];
    const float* fc1b  = (const float*)d_in[12];
    const float* fc2w  = (const float*)d_in[13];
    const float* fc2b  = (const float*)d_in[14];
    const float* emb   = (const float*)d_in[15];
    const float* Wall  = (const float*)d_in[16];
    float* out = (float*)d_out;

    float *c1, *c2, *c3, *c4;
    cudaGetSymbolAddress((void**)&c1, g_c1);
    cudaGetSymbolAddress((void**)&c2, g_c2);
    cudaGetSymbolAddress((void**)&c3, g_c3);
    cudaGetSymbolAddress((void**)&c4, g_c4);

    // R4-verified G config, all-constant dims; 784 blocks each
    conv_split<3, 1,  224, 224, 4,  true ><<<784, 256>>>(rgb, cw1, cb1, c1);
    conv_split<4, 2,  112, 112, 8,  true ><<<784, 256>>>(c1,  cw2, cb2, c2);
    conv_split<8, 4,   56,  56, 16, true ><<<784, 256>>>(c2,  cw3, cb3, c3);
    conv_split<16,8,   28,  28, 32, true ><<<784, 256>>>(c3,  cw4, cb4, c4);

    // conv5 + head fused (arrive-last; loss at the final output element)
    conv5_head_k<<<C5_BLOCKS, 256>>>(c4, cw5, cb5, fc1w, fc1b, fc2w, fc2b, emb,
                                     out + (long long)out_size - 1);

    // big streaming GEMM (byte-identical to the 454.8us best)
    const int TB = 256;
    long long nblocks = (NV + TB - 1) / TB;
    gemm_k<<<(unsigned)nblocks, TB>>>(Wall, out);
}